// round 14
// baseline (speedup 1.0000x reference)
#include <cuda_runtime.h>
#include <cuda_fp16.h>
#include <math_constants.h>
#include <cstdint>

#define BZ   32
#define RVN  16
#define RVL  64
#define H    256
#define NTOK 1024
#define HID  256
#define EPSF 1e-8f
#define NEGV -100000000.0f
#define RSCALE 1024.0f

// ---------------- scratch ----------------------------------------------------
__device__ __align__(16) float g_invb[BZ * NTOK];
__device__ __align__(16) float g_sb_part[16][BZ][H];
__device__ __align__(16) float g_denom[BZ];
__device__ __align__(16) float g_word[BZ * NTOK];
__device__ __align__(16) float g_inva[BZ * NTOK];
__device__ __align__(16) float g_max[BZ * NTOK];
__device__ int g_mask_byte;
// fp16 operands: A plain fp16 (raw); B hi + scaled residual (pre-scaled by 1/||b||)
__device__ __align__(16) __half g_af[BZ * NTOK * H];
__device__ __align__(16) __half g_bh[BZ * NTOK * H];
__device__ __align__(16) __half g_bl[BZ * NTOK * H];

__device__ __forceinline__ bool mask_at(const void* m, int i) {
    if (g_mask_byte) return ((const unsigned char*)m)[i] != 0;
    return ((const unsigned int*)m)[i] != 0u;
}
__device__ __forceinline__ float dot4(float4 a, float4 b) {
    return a.x * b.x + a.y * b.y + a.z * b.z + a.w * b.w;
}
__device__ __forceinline__ void cvt4_a(float4 v, __half* p) {
    __half2* d = (__half2*)p;
    d[0] = __floats2half2_rn(v.x, v.y);
    d[1] = __floats2half2_rn(v.z, v.w);
}
__device__ __forceinline__ void cvt4_b(float4 v, float s, __half* hp, __half* lp) {
    float x0 = v.x * s, x1 = v.y * s, x2 = v.z * s, x3 = v.w * s;
    __half h0 = __float2half_rn(x0), h1 = __float2half_rn(x1);
    __half h2 = __float2half_rn(x2), h3 = __float2half_rn(x3);
    float r0 = (x0 - __half2float(h0)) * RSCALE;
    float r1 = (x1 - __half2float(h1)) * RSCALE;
    float r2 = (x2 - __half2float(h2)) * RSCALE;
    float r3 = (x3 - __half2float(h3)) * RSCALE;
    __half2* hd = (__half2*)hp;
    hd[0] = __halves2half2(h0, h1);
    hd[1] = __halves2half2(h2, h3);
    __half2* ld = (__half2*)lp;
    ld[0] = __floats2half2_rn(r0, r1);
    ld[1] = __floats2half2_rn(r2, r3);
}

__device__ __forceinline__ uint32_t smem_u32(const void* p) {
    uint32_t a;
    asm("{ .reg .u64 t; cvta.to.shared.u64 t, %1; cvt.u32.u64 %0, t; }"
        : "=r"(a) : "l"(p));
    return a;
}
__device__ __forceinline__ void cpa16(uint32_t dst, const void* src) {
    asm volatile("cp.async.cg.shared.global [%0], [%1], 16;" :: "r"(dst), "l"(src));
}
__device__ __forceinline__ void ldsm4(uint32_t addr, uint32_t* r) {
    asm volatile("ldmatrix.sync.aligned.m8n8.x4.shared.b16 {%0,%1,%2,%3}, [%4];"
                 : "=r"(r[0]), "=r"(r[1]), "=r"(r[2]), "=r"(r[3]) : "r"(addr));
}
__device__ __forceinline__ void mma16816h(float* c, const uint32_t* a,
                                          uint32_t b0, uint32_t b1) {
    asm volatile(
        "mma.sync.aligned.m16n8k16.row.col.f32.f16.f16.f32 "
        "{%0,%1,%2,%3}, {%4,%5,%6,%7}, {%8,%9}, {%0,%1,%2,%3};"
        : "+f"(c[0]), "+f"(c[1]), "+f"(c[2]), "+f"(c[3])
        : "r"(a[0]), "r"(a[1]), "r"(a[2]), "r"(a[3]), "r"(b0), "r"(b1));
}

// ---------------- fused mask-width detect + per-batch denom ------------------
__global__ void k_detect_denom(const unsigned char* __restrict__ mbraw,
                               const void* __restrict__ mask_b) {
    __shared__ int mbyte;
    int t = threadIdx.x;  // 1024 threads
    if (t < 32) {
        int cnt = 0;
#pragma unroll
        for (int j = 0; j < 32; j++)
            cnt += mbraw[(t * 32 + j) * 4 + 1] ? 1 : 0;
#pragma unroll
        for (int off = 16; off > 0; off >>= 1)
            cnt += __shfl_xor_sync(0xffffffffu, cnt, off);
        if (t == 0) {
            int v = (cnt > 64) ? 1 : 0;
            g_mask_byte = v;
            mbyte = v;
        }
    }
    __syncthreads();
    int b = t >> 5, lane = t & 31;
    int c = 0;
    for (int q = lane; q < NTOK; q += 32) {
        bool m = mbyte ? (((const unsigned char*)mask_b)[b * NTOK + q] != 0)
                       : (((const unsigned int*)mask_b)[b * NTOK + q] != 0u);
        c += m ? 1 : 0;
    }
#pragma unroll
    for (int off = 16; off > 0; off >>= 1)
        c += __shfl_xor_sync(0xffffffffu, c, off);
    if (lane == 0) g_denom[b] = fmaxf((float)c, 1.0f);
}

// ---------------- fused prep: A blocks (0..511) + B blocks (512..1023) -------
__global__ void k_prep_ab(const float* __restrict__ seq_a,
                          const float* __restrict__ seq_b,
                          const void* __restrict__ mask_a,
                          const void* __restrict__ mask_b,
                          const float* __restrict__ w_word,
                          const float* __restrict__ b_word) {
    __shared__ float s[8][H];
    int bx = blockIdx.x;
    int wid = threadIdx.x >> 5, lane = threadIdx.x & 31;

    if (bx < 512) {  // ---- A: fp16 convert + word + inva ----
        int tok0 = bx * 64;
        const float4* pw = (const float4*)w_word;
        float4 w0 = pw[lane], w1v = pw[lane + 32];
        float bw = b_word[0];
#pragma unroll
        for (int i = 0; i < 8; i++) {
            int tok = tok0 + wid * 8 + i;
            const float4* pa = (const float4*)(seq_a + (size_t)tok * H);
            float4 v0 = pa[lane], v1 = pa[lane + 32];
            float ss = dot4(v0, v0) + dot4(v1, v1);
            float dw = dot4(v0, w0) + dot4(v1, w1v);
#pragma unroll
            for (int off = 16; off > 0; off >>= 1) {
                ss += __shfl_xor_sync(0xffffffffu, ss, off);
                dw += __shfl_xor_sync(0xffffffffu, dw, off);
            }
            if (lane == 0) {
                float ma = mask_at(mask_a, tok) ? 1.0f : 0.0f;
                g_word[tok] = (dw + bw) * ma;
                g_inva[tok] = 1.0f / (sqrtf(ss) + EPSF);
            }
            size_t base = (size_t)tok * H;
            cvt4_a(v0, g_af + base + lane * 4);
            cvt4_a(v1, g_af + base + 128 + lane * 4);
        }
    } else {  // ---- B: normalize, split, masked partial sums ----
        int bi = bx - 512;
        int tok0 = bi * 64;
        int b = tok0 >> 10;
        int chunk = bi & 15;
        float4 acc0 = {0.f, 0.f, 0.f, 0.f}, acc1 = {0.f, 0.f, 0.f, 0.f};
#pragma unroll
        for (int i = 0; i < 8; i++) {
            int tok = tok0 + wid * 8 + i;
            const float4* p = (const float4*)(seq_b + (size_t)tok * H);
            float4 v0 = p[lane], v1 = p[lane + 32];
            float ss = dot4(v0, v0) + dot4(v1, v1);
#pragma unroll
            for (int off = 16; off > 0; off >>= 1)
                ss += __shfl_xor_sync(0xffffffffu, ss, off);
            float ib = 1.0f / (sqrtf(ss) + EPSF);
            if (lane == 0) g_invb[tok] = ib;
            size_t base = (size_t)tok * H;
            cvt4_b(v0, ib, g_bh + base + lane * 4, g_bl + base + lane * 4);
            cvt4_b(v1, ib, g_bh + base + 128 + lane * 4, g_bl + base + 128 + lane * 4);
            if (mask_at(mask_b, tok)) {
                acc0.x += v0.x * ib; acc0.y += v0.y * ib;
                acc0.z += v0.z * ib; acc0.w += v0.w * ib;
                acc1.x += v1.x * ib; acc1.y += v1.y * ib;
                acc1.z += v1.z * ib; acc1.w += v1.w * ib;
            }
        }
        *(float4*)&s[wid][lane * 4] = acc0;
        *(float4*)&s[wid][128 + lane * 4] = acc1;
        __syncthreads();
        int t = threadIdx.x;
        float sum = 0.f;
#pragma unroll
        for (int w = 0; w < 8; w++) sum += s[w][t];
        g_sb_part[chunk][b][t] = sum;
    }
}

// ---------------- HMMA GEMM (fp16 2-pass), 2 CTAs/SM, single wave ------------
#define OFF_B0 4096     // uint4 units
#define B_STAGE 1024    // uint4 units (16KB)
#define SMEM_BYTES ((4096 + 3 * B_STAGE) * 16)   // 112KB

__global__ __launch_bounds__(256, 2) void k_gemm_max() {
    extern __shared__ __align__(128) unsigned char smraw[];
    const uint32_t smb = smem_u32(smraw);

    const int b   = blockIdx.y;
    const int m0  = blockIdx.x * 128;
    const int tid = threadIdx.x, wid = tid >> 5, lane = tid & 31;
    const int wm = wid & 3, wn = wid >> 2;
    const int g = lane >> 3, ril = lane & 7;

    const uint4* gaf = (const uint4*)g_af + (size_t)(b * NTOK + m0) * 32;
    const uint4* gbh = (const uint4*)g_bh + (size_t)b * NTOK * 32;
    const uint4* gbl = (const uint4*)g_bl + (size_t)b * NTOK * 32;

    // A: 128 rows x 32 uint4, swizzled; one cp.async group
#pragma unroll
    for (int i = 0; i < 16; i++) {
        int idx = tid + i * 256;
        int r = idx >> 5, c = idx & 31, cs = c ^ (r & 7);
        cpa16(smb + (uint32_t)(r * 32 + cs) * 16, gaf + r * 32 + c);
    }
    asm volatile("cp.async.commit_group;" ::: "memory");

    // B chunk loader: ii -> n-chunk ii>>2 (64 rows), k-chunk ii&3 (64 cols)
    auto loadB = [&](int ii) {
        int nt = ii >> 2, kc = ii & 3, buf = ii % 3;
        uint32_t base = smb + (uint32_t)(OFF_B0 + buf * B_STAGE) * 16;
#pragma unroll
        for (int i = 0; i < 2; i++) {
            int idx = tid + i * 256;
            int n = idx >> 3, c = idx & 7, cs = c ^ (n & 7);
            size_t gi = (size_t)(nt * 64 + n) * 32 + kc * 8 + c;
            cpa16(base + (uint32_t)(n * 8 + cs) * 16, gbh + gi);
            cpa16(base + (uint32_t)(512 + n * 8 + cs) * 16, gbl + gi);
        }
        asm volatile("cp.async.commit_group;" ::: "memory");
    };
    loadB(0);
    loadB(1);

    float pm[2][2];
    pm[0][0] = pm[0][1] = pm[1][0] = pm[1][1] = -CUDART_INF_F;
    float accH[2][4][4], accL[2][4][4];

    uint32_t fa[2][2][4], fbh[2][2][4], fbl[2][2][4];

    auto ldfrags = [&](int kc, int ks, int pp, int buf) {
#pragma unroll
        for (int mt = 0; mt < 2; mt++) {
            int r = wm * 32 + mt * 16 + ((g & 1) << 3) + ril;
            int c = kc * 8 + ks * 2 + (g >> 1);
            int cs = c ^ (r & 7);
            ldsm4(smb + (uint32_t)(r * 32 + cs) * 16, fa[pp][mt]);
        }
#pragma unroll
        for (int np = 0; np < 2; np++) {
            int r = wn * 32 + np * 16 + ((g & 1) << 3) + ril;
            int c = ks * 2 + (g >> 1);
            int cs = c ^ (r & 7);
            uint32_t base = (uint32_t)(OFF_B0 + buf * B_STAGE + r * 8 + cs);
            ldsm4(smb + base * 16, fbh[pp][np]);
            ldsm4(smb + (base + 512) * 16, fbl[pp][np]);
        }
    };

    for (int ii = 0; ii < 64; ii++) {
        int kc = ii & 3, buf = ii % 3;
        if (ii < 63) {
            asm volatile("cp.async.wait_group 1;" ::: "memory");
        } else {
            asm volatile("cp.async.wait_group 0;" ::: "memory");
        }
        __syncthreads();
        if (ii <= 61) loadB(ii + 2);

        if (kc == 0) {
#pragma unroll
            for (int mt = 0; mt < 2; mt++)
#pragma unroll
                for (int n = 0; n < 4; n++)
#pragma unroll
                    for (int q = 0; q < 4; q++) {
                        accH[mt][n][q] = 0.f;
                        accL[mt][n][q] = 0.f;
                    }
        }

        ldfrags(kc, 0, 0, buf);
#pragma unroll
        for (int ks = 0; ks < 4; ks++) {
            int cur = ks & 1;
            if (ks < 3) ldfrags(kc, ks + 1, cur ^ 1, buf);
#pragma unroll
            for (int mt = 0; mt < 2; mt++)
#pragma unroll
                for (int np = 0; np < 2; np++)
#pragma unroll
                    for (int sub = 0; sub < 2; sub++) {
                        mma16816h(accH[mt][np * 2 + sub], fa[cur][mt],
                                  fbh[cur][np][sub], fbh[cur][np][sub + 2]);
                        mma16816h(accL[mt][np * 2 + sub], fa[cur][mt],
                                  fbl[cur][np][sub], fbl[cur][np][sub + 2]);
                    }
        }

        if (kc == 3) {
#pragma unroll
            for (int mt = 0; mt < 2; mt++)
#pragma unroll
                for (int n = 0; n < 4; n++) {
                    float v0 = accH[mt][n][0] + accL[mt][n][0] * (1.0f / RSCALE);
                    float v1 = accH[mt][n][1] + accL[mt][n][1] * (1.0f / RSCALE);
                    float v2 = accH[mt][n][2] + accL[mt][n][2] * (1.0f / RSCALE);
                    float v3 = accH[mt][n][3] + accL[mt][n][3] * (1.0f / RSCALE);
                    pm[mt][0] = fmaxf(pm[mt][0], fmaxf(v0, v1));
                    pm[mt][1] = fmaxf(pm[mt][1], fmaxf(v2, v3));
                }
        }
    }

    __syncthreads();
    float* mred = (float*)smraw;
#pragma unroll
    for (int mt = 0; mt < 2; mt++)
#pragma unroll
        for (int hf = 0; hf < 2; hf++) {
            float v = pm[mt][hf];
            v = fmaxf(v, __shfl_xor_sync(0xffffffffu, v, 1));
            v = fmaxf(v, __shfl_xor_sync(0xffffffffu, v, 2));
            if ((lane & 3) == 0)
                mred[(wm * 32 + mt * 16 + hf * 8 + (lane >> 2)) * 2 + wn] = v;
        }
    __syncthreads();
    if (tid < 128) {
        float v = fmaxf(mred[tid * 2], mred[tid * 2 + 1]);
        int row = b * NTOK + m0 + tid;
        g_max[row] = v * g_inva[row];
    }
}

// ---------------- final: smem A-tile + parallel softmax ----------------------
// 512 blocks (one per (b,r)). A tile (64x256 f32 = 64KB) staged via cp.async.
#define FIN_SMEM (RVL * H * 4)   // 65536

__global__ __launch_bounds__(256) void k_final(
        const float* __restrict__ seq_a,
        const void* __restrict__ mask_a,
        const float* __restrict__ w1, const float* __restrict__ b1,
        const float* __restrict__ w2, const float* __restrict__ b2,
        float* __restrict__ out) {
    extern __shared__ __align__(16) float As[];   // [64][256]
    __shared__ float wrd[64], mn[64], mx[64], feat[128], attn[64], sbs[H];
    __shared__ float rr[8], sm4v[4];

    int br = blockIdx.x;
    int t  = threadIdx.x;
    int b  = br >> 4;
    int wid = t >> 5, lane = t & 31;

    // stage A tile (4096 uint4)
    {
        uint32_t sA = smem_u32(As);
        const uint4* Ag = (const uint4*)(seq_a + (size_t)br * RVL * H);
#pragma unroll
        for (int i = 0; i < 16; i++) {
            int idx = t + i * 256;
            cpa16(sA + (uint32_t)idx * 16, Ag + idx);
        }
        asm volatile("cp.async.commit_group;" ::: "memory");
    }

    if (t < 64) {
        int tok = br * RVL + t;
        wrd[t] = g_word[tok];
        mx[t]  = g_max[tok];
    }
    {
        float s = 0.f;
#pragma unroll
        for (int c = 0; c < 16; c++) s += g_sb_part[c][b][t];
        sbs[t] = s;
    }
    __syncthreads();

    // ---- parallel masked softmax over 64 tokens (threads 0..63) ----
    float sft = NEGV, ev = 0.f;
    if (t < 64)
        sft = mask_at(mask_a, br * RVL + t) ? wrd[t] : NEGV;
    if (t < 64) {
        float m = sft;
#pragma unroll
        for (int off = 16; off > 0; off >>= 1)
            m = fmaxf(m, __shfl_xor_sync(0xffffffffu, m, off));
        if (lane == 0) sm4v[wid] = m;
    }
    __syncthreads();
    if (t < 64) {
        float M = fmaxf(sm4v[0], sm4v[1]);
        ev = expf(sft - M);
        float s = ev;
#pragma unroll
        for (int off = 16; off > 0; off >>= 1)
            s += __shfl_xor_sync(0xffffffffu, s, off);
        if (lane == 0) sm4v[2 + wid] = s;
    }
    __syncthreads();
    if (t < 64) attn[t] = ev / (sm4v[2] + sm4v[3]);

    // wait for A tile
    asm volatile("cp.async.wait_group 0;" ::: "memory");
    __syncthreads();

    // ---- masked mean from smem A ----
    {
        float dnm = g_denom[b];
        float4 sb0 = *(float4*)&sbs[lane * 4];
        float4 sb1 = *(float4*)&sbs[128 + lane * 4];
#pragma unroll
        for (int i = 0; i < 8; i++) {
            int l = wid * 8 + i;
            const float4* pa = (const float4*)(As + l * H);
            float4 v0 = pa[lane], v1 = pa[lane + 32];
            float ds = dot4(v0, sb0) + dot4(v1, sb1);
#pragma unroll
            for (int off = 16; off > 0; off >>= 1)
                ds += __shfl_xor_sync(0xffffffffu, ds, off);
            if (lane == 0) mn[l] = g_inva[br * RVL + l] * ds / dnm;
        }
    }
    __syncthreads();

    if (t < 128) {
        int l = t >> 1;
        feat[t] = ((t & 1) ? mx[l] : mn[l]) * wrd[l];
    }
    __syncthreads();

    // ---- MLP: hid = tanh(feat @ w1 + b1); logit = hid @ w2 + b2 ----
    {
        float acc = b1[t];
#pragma unroll 4
        for (int f = 0; f < 128; f++) acc += feat[f] * w1[f * HID + t];
        float v = tanhf(acc) * w2[t];
#pragma unroll
        for (int off = 16; off > 0; off >>= 1)
            v += __shfl_xor_sync(0xffffffffu, v, off);
        if (lane == 0) rr[wid] = v;
    }
    __syncthreads();
    if (t == 0) {
        float s = 0.f;
#pragma unroll
        for (int w = 0; w < 8; w++) s += rr[w];
        out[br] = s + b2[0];
    }

    // ---- aggregation from smem A ----
    float agg = 0.f;
#pragma unroll 8
    for (int l = 0; l < 64; l++) agg += attn[l] * As[l * H + t];
    out[BZ * RVN + br * H + t] = agg;
}

// ---------------- launch ------------------------------------------------------
extern "C" void kernel_launch(void* const* d_in, const int* in_sizes, int n_in,
                              void* d_out, int out_size) {
    const float* seq_a = (const float*)d_in[0];
    const float* seq_b = (const float*)d_in[1];
    const void*  mask_a = d_in[2];
    const void*  mask_b = d_in[3];
    const float* w_word = (const float*)d_in[4];
    const float* b_word = (const float*)d_in[5];
    const float* w1 = (const float*)d_in[6];
    const float* b1 = (const float*)d_in[7];
    const float* w2 = (const float*)d_in[8];
    const float* b2 = (const float*)d_in[9];
    float* out = (float*)d_out;

    cudaFuncSetAttribute(k_gemm_max, cudaFuncAttributeMaxDynamicSharedMemorySize,
                         SMEM_BYTES);
    cudaFuncSetAttribute(k_final, cudaFuncAttributeMaxDynamicSharedMemorySize,
                         FIN_SMEM);

    k_detect_denom<<<1, 1024>>>((const unsigned char*)mask_b, mask_b);
    k_prep_ab<<<1024, 256>>>(seq_a, seq_b, mask_a, mask_b, w_word, b_word);
    k_gemm_max<<<dim3(8, BZ), 256, SMEM_BYTES>>>();
    k_final<<<BZ * RVN, 256, FIN_SMEM>>>(seq_a, mask_a, w1, b1, w2, b2, out);
}

// round 15
// speedup vs baseline: 1.0494x; 1.0494x over previous
#include <cuda_runtime.h>
#include <cuda_fp16.h>
#include <math_constants.h>
#include <cstdint>

#define BZ   32
#define RVN  16
#define RVL  64
#define H    256
#define NTOK 1024
#define HID  256
#define EPSF 1e-8f
#define NEGV -100000000.0f
#define RSCALE 1024.0f

// ---------------- scratch ----------------------------------------------------
__device__ __align__(16) float g_invb[BZ * NTOK];
__device__ __align__(16) float g_sb_part[16][BZ][H];
__device__ __align__(16) float g_denom[BZ];
__device__ __align__(16) float g_word[BZ * NTOK];
__device__ __align__(16) float g_inva[BZ * NTOK];
__device__ __align__(16) float g_max[BZ * NTOK];
__device__ int g_mask_byte;
// fp16 operands: A plain fp16 (raw); B hi + scaled residual (pre-scaled by 1/||b||)
__device__ __align__(16) __half g_af[BZ * NTOK * H];
__device__ __align__(16) __half g_bh[BZ * NTOK * H];
__device__ __align__(16) __half g_bl[BZ * NTOK * H];

__device__ __forceinline__ bool mask_at(const void* m, int i) {
    if (g_mask_byte) return ((const unsigned char*)m)[i] != 0;
    return ((const unsigned int*)m)[i] != 0u;
}
__device__ __forceinline__ float dot4(float4 a, float4 b) {
    return a.x * b.x + a.y * b.y + a.z * b.z + a.w * b.w;
}
__device__ __forceinline__ void cvt4_a(float4 v, __half* p) {
    __half2* d = (__half2*)p;
    d[0] = __floats2half2_rn(v.x, v.y);
    d[1] = __floats2half2_rn(v.z, v.w);
}
__device__ __forceinline__ void cvt4_b(float4 v, float s, __half* hp, __half* lp) {
    float x0 = v.x * s, x1 = v.y * s, x2 = v.z * s, x3 = v.w * s;
    __half h0 = __float2half_rn(x0), h1 = __float2half_rn(x1);
    __half h2 = __float2half_rn(x2), h3 = __float2half_rn(x3);
    float r0 = (x0 - __half2float(h0)) * RSCALE;
    float r1 = (x1 - __half2float(h1)) * RSCALE;
    float r2 = (x2 - __half2float(h2)) * RSCALE;
    float r3 = (x3 - __half2float(h3)) * RSCALE;
    __half2* hd = (__half2*)hp;
    hd[0] = __halves2half2(h0, h1);
    hd[1] = __halves2half2(h2, h3);
    __half2* ld = (__half2*)lp;
    ld[0] = __floats2half2_rn(r0, r1);
    ld[1] = __floats2half2_rn(r2, r3);
}

__device__ __forceinline__ uint32_t smem_u32(const void* p) {
    uint32_t a;
    asm("{ .reg .u64 t; cvta.to.shared.u64 t, %1; cvt.u32.u64 %0, t; }"
        : "=r"(a) : "l"(p));
    return a;
}
__device__ __forceinline__ void cpa16(uint32_t dst, const void* src) {
    asm volatile("cp.async.cg.shared.global [%0], [%1], 16;" :: "r"(dst), "l"(src));
}
__device__ __forceinline__ void ldsm4(uint32_t addr, uint32_t* r) {
    asm volatile("ldmatrix.sync.aligned.m8n8.x4.shared.b16 {%0,%1,%2,%3}, [%4];"
                 : "=r"(r[0]), "=r"(r[1]), "=r"(r[2]), "=r"(r[3]) : "r"(addr));
}
__device__ __forceinline__ void mma16816h(float* c, const uint32_t* a,
                                          uint32_t b0, uint32_t b1) {
    asm volatile(
        "mma.sync.aligned.m16n8k16.row.col.f32.f16.f16.f32 "
        "{%0,%1,%2,%3}, {%4,%5,%6,%7}, {%8,%9}, {%0,%1,%2,%3};"
        : "+f"(c[0]), "+f"(c[1]), "+f"(c[2]), "+f"(c[3])
        : "r"(a[0]), "r"(a[1]), "r"(a[2]), "r"(a[3]), "r"(b0), "r"(b1));
}

// ---------------- fused mask-width detect + per-batch denom ------------------
__global__ void k_detect_denom(const unsigned char* __restrict__ mbraw,
                               const void* __restrict__ mask_b) {
    __shared__ int mbyte;
    int t = threadIdx.x;  // 1024 threads
    if (t < 32) {
        int cnt = 0;
#pragma unroll
        for (int j = 0; j < 32; j++)
            cnt += mbraw[(t * 32 + j) * 4 + 1] ? 1 : 0;
#pragma unroll
        for (int off = 16; off > 0; off >>= 1)
            cnt += __shfl_xor_sync(0xffffffffu, cnt, off);
        if (t == 0) {
            int v = (cnt > 64) ? 1 : 0;
            g_mask_byte = v;
            mbyte = v;
        }
    }
    __syncthreads();
    int b = t >> 5, lane = t & 31;
    int c = 0;
    for (int q = lane; q < NTOK; q += 32) {
        bool m = mbyte ? (((const unsigned char*)mask_b)[b * NTOK + q] != 0)
                       : (((const unsigned int*)mask_b)[b * NTOK + q] != 0u);
        c += m ? 1 : 0;
    }
#pragma unroll
    for (int off = 16; off > 0; off >>= 1)
        c += __shfl_xor_sync(0xffffffffu, c, off);
    if (lane == 0) g_denom[b] = fmaxf((float)c, 1.0f);
}

// ---------------- fused prep: A blocks (0..511) + B blocks (512..1023) -------
__global__ void k_prep_ab(const float* __restrict__ seq_a,
                          const float* __restrict__ seq_b,
                          const void* __restrict__ mask_a,
                          const void* __restrict__ mask_b,
                          const float* __restrict__ w_word,
                          const float* __restrict__ b_word) {
    __shared__ float s[8][H];
    int bx = blockIdx.x;
    int wid = threadIdx.x >> 5, lane = threadIdx.x & 31;

    if (bx < 512) {  // ---- A: fp16 convert + word + inva ----
        int tok0 = bx * 64;
        const float4* pw = (const float4*)w_word;
        float4 w0 = pw[lane], w1v = pw[lane + 32];
        float bw = b_word[0];
#pragma unroll
        for (int i = 0; i < 8; i++) {
            int tok = tok0 + wid * 8 + i;
            const float4* pa = (const float4*)(seq_a + (size_t)tok * H);
            float4 v0 = pa[lane], v1 = pa[lane + 32];
            float ss = dot4(v0, v0) + dot4(v1, v1);
            float dw = dot4(v0, w0) + dot4(v1, w1v);
#pragma unroll
            for (int off = 16; off > 0; off >>= 1) {
                ss += __shfl_xor_sync(0xffffffffu, ss, off);
                dw += __shfl_xor_sync(0xffffffffu, dw, off);
            }
            if (lane == 0) {
                float ma = mask_at(mask_a, tok) ? 1.0f : 0.0f;
                g_word[tok] = (dw + bw) * ma;
                g_inva[tok] = 1.0f / (sqrtf(ss) + EPSF);
            }
            size_t base = (size_t)tok * H;
            cvt4_a(v0, g_af + base + lane * 4);
            cvt4_a(v1, g_af + base + 128 + lane * 4);
        }
    } else {  // ---- B: normalize, split, masked partial sums ----
        int bi = bx - 512;
        int tok0 = bi * 64;
        int b = tok0 >> 10;
        int chunk = bi & 15;
        float4 acc0 = {0.f, 0.f, 0.f, 0.f}, acc1 = {0.f, 0.f, 0.f, 0.f};
#pragma unroll
        for (int i = 0; i < 8; i++) {
            int tok = tok0 + wid * 8 + i;
            const float4* p = (const float4*)(seq_b + (size_t)tok * H);
            float4 v0 = p[lane], v1 = p[lane + 32];
            float ss = dot4(v0, v0) + dot4(v1, v1);
#pragma unroll
            for (int off = 16; off > 0; off >>= 1)
                ss += __shfl_xor_sync(0xffffffffu, ss, off);
            float ib = 1.0f / (sqrtf(ss) + EPSF);
            if (lane == 0) g_invb[tok] = ib;
            size_t base = (size_t)tok * H;
            cvt4_b(v0, ib, g_bh + base + lane * 4, g_bl + base + lane * 4);
            cvt4_b(v1, ib, g_bh + base + 128 + lane * 4, g_bl + base + 128 + lane * 4);
            if (mask_at(mask_b, tok)) {
                acc0.x += v0.x * ib; acc0.y += v0.y * ib;
                acc0.z += v0.z * ib; acc0.w += v0.w * ib;
                acc1.x += v1.x * ib; acc1.y += v1.y * ib;
                acc1.z += v1.z * ib; acc1.w += v1.w * ib;
            }
        }
        *(float4*)&s[wid][lane * 4] = acc0;
        *(float4*)&s[wid][128 + lane * 4] = acc1;
        __syncthreads();
        int t = threadIdx.x;
        float sum = 0.f;
#pragma unroll
        for (int w = 0; w < 8; w++) sum += s[w][t];
        g_sb_part[chunk][b][t] = sum;
    }
}

// ---------------- HMMA GEMM (fp16 2-pass), 2 CTAs/SM, single wave ------------
#define OFF_B0 4096     // uint4 units
#define B_STAGE 1024    // uint4 units (16KB)
#define SMEM_BYTES ((4096 + 3 * B_STAGE) * 16)   // 112KB

__global__ __launch_bounds__(256, 2) void k_gemm_max() {
    extern __shared__ __align__(128) unsigned char smraw[];
    const uint32_t smb = smem_u32(smraw);

    const int b   = blockIdx.y;
    const int m0  = blockIdx.x * 128;
    const int tid = threadIdx.x, wid = tid >> 5, lane = tid & 31;
    const int wm = wid & 3, wn = wid >> 2;
    const int g = lane >> 3, ril = lane & 7;

    const uint4* gaf = (const uint4*)g_af + (size_t)(b * NTOK + m0) * 32;
    const uint4* gbh = (const uint4*)g_bh + (size_t)b * NTOK * 32;
    const uint4* gbl = (const uint4*)g_bl + (size_t)b * NTOK * 32;

    // A: 128 rows x 32 uint4, swizzled; one cp.async group
#pragma unroll
    for (int i = 0; i < 16; i++) {
        int idx = tid + i * 256;
        int r = idx >> 5, c = idx & 31, cs = c ^ (r & 7);
        cpa16(smb + (uint32_t)(r * 32 + cs) * 16, gaf + r * 32 + c);
    }
    asm volatile("cp.async.commit_group;" ::: "memory");

    // B chunk loader: ii -> n-chunk ii>>2 (64 rows), k-chunk ii&3 (64 cols)
    auto loadB = [&](int ii) {
        int nt = ii >> 2, kc = ii & 3, buf = ii % 3;
        uint32_t base = smb + (uint32_t)(OFF_B0 + buf * B_STAGE) * 16;
#pragma unroll
        for (int i = 0; i < 2; i++) {
            int idx = tid + i * 256;
            int n = idx >> 3, c = idx & 7, cs = c ^ (n & 7);
            size_t gi = (size_t)(nt * 64 + n) * 32 + kc * 8 + c;
            cpa16(base + (uint32_t)(n * 8 + cs) * 16, gbh + gi);
            cpa16(base + (uint32_t)(512 + n * 8 + cs) * 16, gbl + gi);
        }
        asm volatile("cp.async.commit_group;" ::: "memory");
    };
    loadB(0);
    loadB(1);

    float pm[2][2];
    pm[0][0] = pm[0][1] = pm[1][0] = pm[1][1] = -CUDART_INF_F;
    float accH[2][4][4], accL[2][4][4];

    uint32_t fa[2][2][4], fbh[2][2][4], fbl[2][2][4];

    auto ldfrags = [&](int kc, int ks, int pp, int buf) {
#pragma unroll
        for (int mt = 0; mt < 2; mt++) {
            int r = wm * 32 + mt * 16 + ((g & 1) << 3) + ril;
            int c = kc * 8 + ks * 2 + (g >> 1);
            int cs = c ^ (r & 7);
            ldsm4(smb + (uint32_t)(r * 32 + cs) * 16, fa[pp][mt]);
        }
#pragma unroll
        for (int np = 0; np < 2; np++) {
            int r = wn * 32 + np * 16 + ((g & 1) << 3) + ril;
            int c = ks * 2 + (g >> 1);
            int cs = c ^ (r & 7);
            uint32_t base = (uint32_t)(OFF_B0 + buf * B_STAGE + r * 8 + cs);
            ldsm4(smb + base * 16, fbh[pp][np]);
            ldsm4(smb + (base + 512) * 16, fbl[pp][np]);
        }
    };

    for (int ii = 0; ii < 64; ii++) {
        int kc = ii & 3, buf = ii % 3;
        if (ii < 63) {
            asm volatile("cp.async.wait_group 1;" ::: "memory");
        } else {
            asm volatile("cp.async.wait_group 0;" ::: "memory");
        }
        __syncthreads();
        if (ii <= 61) loadB(ii + 2);

        if (kc == 0) {
#pragma unroll
            for (int mt = 0; mt < 2; mt++)
#pragma unroll
                for (int n = 0; n < 4; n++)
#pragma unroll
                    for (int q = 0; q < 4; q++) {
                        accH[mt][n][q] = 0.f;
                        accL[mt][n][q] = 0.f;
                    }
        }

        ldfrags(kc, 0, 0, buf);
#pragma unroll
        for (int ks = 0; ks < 4; ks++) {
            int cur = ks & 1;
            if (ks < 3) ldfrags(kc, ks + 1, cur ^ 1, buf);
#pragma unroll
            for (int mt = 0; mt < 2; mt++)
#pragma unroll
                for (int np = 0; np < 2; np++)
#pragma unroll
                    for (int sub = 0; sub < 2; sub++) {
                        mma16816h(accH[mt][np * 2 + sub], fa[cur][mt],
                                  fbh[cur][np][sub], fbh[cur][np][sub + 2]);
                        mma16816h(accL[mt][np * 2 + sub], fa[cur][mt],
                                  fbl[cur][np][sub], fbl[cur][np][sub + 2]);
                    }
        }

        if (kc == 3) {
#pragma unroll
            for (int mt = 0; mt < 2; mt++)
#pragma unroll
                for (int n = 0; n < 4; n++) {
                    float v0 = accH[mt][n][0] + accL[mt][n][0] * (1.0f / RSCALE);
                    float v1 = accH[mt][n][1] + accL[mt][n][1] * (1.0f / RSCALE);
                    float v2 = accH[mt][n][2] + accL[mt][n][2] * (1.0f / RSCALE);
                    float v3 = accH[mt][n][3] + accL[mt][n][3] * (1.0f / RSCALE);
                    pm[mt][0] = fmaxf(pm[mt][0], fmaxf(v0, v1));
                    pm[mt][1] = fmaxf(pm[mt][1], fmaxf(v2, v3));
                }
        }
    }

    __syncthreads();
    float* mred = (float*)smraw;
#pragma unroll
    for (int mt = 0; mt < 2; mt++)
#pragma unroll
        for (int hf = 0; hf < 2; hf++) {
            float v = pm[mt][hf];
            v = fmaxf(v, __shfl_xor_sync(0xffffffffu, v, 1));
            v = fmaxf(v, __shfl_xor_sync(0xffffffffu, v, 2));
            if ((lane & 3) == 0)
                mred[(wm * 32 + mt * 16 + hf * 8 + (lane >> 2)) * 2 + wn] = v;
        }
    __syncthreads();
    if (tid < 128) {
        float v = fmaxf(mred[tid * 2], mred[tid * 2 + 1]);
        int row = b * NTOK + m0 + tid;
        g_max[row] = v * g_inva[row];
    }
}

// ---------------- final: parallel softmax + MLP-friendly mean ----------------
__global__ __launch_bounds__(256) void k_final(
        const float* __restrict__ seq_a,
        const void* __restrict__ mask_a,
        const float* __restrict__ w1, const float* __restrict__ b1,
        const float* __restrict__ w2, const float* __restrict__ b2,
        float* __restrict__ out) {
    __shared__ float wrd[64], mn[64], mx[64], feat[128], attn[64], sbs[H];
    __shared__ float rr[8], sm4v[4];

    int br = blockIdx.x;
    int t  = threadIdx.x;
    int b  = br >> 4;
    int wid = t >> 5, lane = t & 31;

    if (t < 64) {
        int tok = br * RVL + t;
        wrd[t] = g_word[tok];
        mx[t]  = g_max[tok];
    }
    {
        float s = 0.f;
#pragma unroll
        for (int c = 0; c < 16; c++) s += g_sb_part[c][b][t];
        sbs[t] = s;
    }
    __syncthreads();

    // ---- parallel masked softmax over 64 tokens (threads 0..63) ----
    float sft = NEGV, ev = 0.f;
    if (t < 64)
        sft = mask_at(mask_a, br * RVL + t) ? wrd[t] : NEGV;
    if (t < 64) {
        float m = sft;
#pragma unroll
        for (int off = 16; off > 0; off >>= 1)
            m = fmaxf(m, __shfl_xor_sync(0xffffffffu, m, off));
        if (lane == 0) sm4v[wid] = m;
    }
    __syncthreads();
    if (t < 64) {
        float M = fmaxf(sm4v[0], sm4v[1]);
        ev = expf(sft - M);
        float s = ev;
#pragma unroll
        for (int off = 16; off > 0; off >>= 1)
            s += __shfl_xor_sync(0xffffffffu, s, off);
        if (lane == 0) sm4v[2 + wid] = s;
    }
    __syncthreads();
    if (t < 64) attn[t] = ev / (sm4v[2] + sm4v[3]);

    // ---- masked mean: thread = (row t>>2, quarter t&3); 16 independent LDG.128
    {
        int row = t >> 2, q = t & 3;
        const float4* pa = (const float4*)(seq_a + ((size_t)(br * RVL + row)) * H) + q * 16;
        const float4* sq = (const float4*)(sbs + q * 64);
        float ds = 0.f;
#pragma unroll
        for (int j = 0; j < 16; j++) ds += dot4(pa[j], sq[j]);
        ds += __shfl_xor_sync(0xffffffffu, ds, 1);
        ds += __shfl_xor_sync(0xffffffffu, ds, 2);
        if (q == 0) mn[row] = g_inva[br * RVL + row] * ds / g_denom[b];
    }
    __syncthreads();

    if (t < 128) {
        int l = t >> 1;
        feat[t] = ((t & 1) ? mx[l] : mn[l]) * wrd[l];
    }
    __syncthreads();

    // ---- MLP: hid = tanh(feat @ w1 + b1); logit = hid @ w2 + b2 ----
    {
        float acc = b1[t];
#pragma unroll 4
        for (int f = 0; f < 128; f++) acc += feat[f] * w1[f * HID + t];
        float v = tanhf(acc) * w2[t];
#pragma unroll
        for (int off = 16; off > 0; off >>= 1)
            v += __shfl_xor_sync(0xffffffffu, v, off);
        if (lane == 0) rr[wid] = v;
    }
    __syncthreads();
    if (t == 0) {
        float s = 0.f;
#pragma unroll
        for (int w = 0; w < 8; w++) s += rr[w];
        out[br] = s + b2[0];
    }

    // ---- aggregation: column t over 64 rows, 8-load batches ----
    {
        const float* A = seq_a + (size_t)br * RVL * H + t;
        float agg = 0.f;
#pragma unroll
        for (int gq = 0; gq < 8; gq++) {
            float v0 = A[(gq * 8 + 0) * H], v1 = A[(gq * 8 + 1) * H];
            float v2 = A[(gq * 8 + 2) * H], v3 = A[(gq * 8 + 3) * H];
            float v4 = A[(gq * 8 + 4) * H], v5 = A[(gq * 8 + 5) * H];
            float v6 = A[(gq * 8 + 6) * H], v7 = A[(gq * 8 + 7) * H];
            agg += attn[gq * 8 + 0] * v0 + attn[gq * 8 + 1] * v1 +
                   attn[gq * 8 + 2] * v2 + attn[gq * 8 + 3] * v3 +
                   attn[gq * 8 + 4] * v4 + attn[gq * 8 + 5] * v5 +
                   attn[gq * 8 + 6] * v6 + attn[gq * 8 + 7] * v7;
        }
        out[BZ * RVN + br * H + t] = agg;
    }
}

// ---------------- launch ------------------------------------------------------
extern "C" void kernel_launch(void* const* d_in, const int* in_sizes, int n_in,
                              void* d_out, int out_size) {
    const float* seq_a = (const float*)d_in[0];
    const float* seq_b = (const float*)d_in[1];
    const void*  mask_a = d_in[2];
    const void*  mask_b = d_in[3];
    const float* w_word = (const float*)d_in[4];
    const float* b_word = (const float*)d_in[5];
    const float* w1 = (const float*)d_in[6];
    const float* b1 = (const float*)d_in[7];
    const float* w2 = (const float*)d_in[8];
    const float* b2 = (const float*)d_in[9];
    float* out = (float*)d_out;

    cudaFuncSetAttribute(k_gemm_max, cudaFuncAttributeMaxDynamicSharedMemorySize,
                         SMEM_BYTES);

    k_detect_denom<<<1, 1024>>>((const unsigned char*)mask_b, mask_b);
    k_prep_ab<<<1024, 256>>>(seq_a, seq_b, mask_a, mask_b, w_word, b_word);
    k_gemm_max<<<dim3(8, BZ), 256, SMEM_BYTES>>>();
    k_final<<<BZ * RVN, 256>>>(seq_a, mask_a, w1, b1, w2, b2, out);
}

// round 16
// speedup vs baseline: 1.5388x; 1.4663x over previous
#include <cuda_runtime.h>
#include <cuda_fp16.h>
#include <math_constants.h>
#include <cstdint>

#define BZ   32
#define RVN  16
#define RVL  64
#define H    256
#define NTOK 1024
#define HID  256
#define EPSF 1e-8f
#define NEGV -100000000.0f

// ---------------- scratch ----------------------------------------------------
__device__ __align__(16) float g_sb_part[16][BZ][H];
__device__ __align__(16) float g_word[BZ * NTOK];
__device__ __align__(16) float g_inva[BZ * NTOK];
__device__ __align__(16) float g_max[BZ * NTOK];
// fp16 operands: A raw fp16; B pre-scaled by 1/||b|| fp16 (single precision pass)
__device__ __align__(16) __half g_af[BZ * NTOK * H];
__device__ __align__(16) __half g_bh[BZ * NTOK * H];

// Warp-local mask dtype probe: for uint8-bool masks (density 0.9), bytes 4i+1
// are element values (nonzero w.p. 0.9); for int32/float32 they are always 0.
__device__ __forceinline__ bool probe_byte_mask(const void* m) {
    int lane = threadIdx.x & 31;
    unsigned char v = ((const unsigned char*)m)[lane * 4 + 1];
    return __popc(__ballot_sync(0xffffffffu, v != 0)) >= 4;
}
__device__ __forceinline__ bool mask_at(const void* m, int i, bool isbyte) {
    if (isbyte) return ((const unsigned char*)m)[i] != 0;
    return ((const unsigned int*)m)[i] != 0u;  // int32 1/0 and float32 1.0/0.0
}
__device__ __forceinline__ float dot4(float4 a, float4 b) {
    return a.x * b.x + a.y * b.y + a.z * b.z + a.w * b.w;
}
__device__ __forceinline__ void cvt4h(float4 v, float s, __half* p) {
    __half2* d = (__half2*)p;
    d[0] = __floats2half2_rn(v.x * s, v.y * s);
    d[1] = __floats2half2_rn(v.z * s, v.w * s);
}

__device__ __forceinline__ uint32_t smem_u32(const void* p) {
    uint32_t a;
    asm("{ .reg .u64 t; cvta.to.shared.u64 t, %1; cvt.u32.u64 %0, t; }"
        : "=r"(a) : "l"(p));
    return a;
}
__device__ __forceinline__ void cpa16(uint32_t dst, const void* src) {
    asm volatile("cp.async.cg.shared.global [%0], [%1], 16;" :: "r"(dst), "l"(src));
}
__device__ __forceinline__ void ldsm4(uint32_t addr, uint32_t* r) {
    asm volatile("ldmatrix.sync.aligned.m8n8.x4.shared.b16 {%0,%1,%2,%3}, [%4];"
                 : "=r"(r[0]), "=r"(r[1]), "=r"(r[2]), "=r"(r[3]) : "r"(addr));
}
__device__ __forceinline__ void mma16816h(float* c, const uint32_t* a,
                                          uint32_t b0, uint32_t b1) {
    asm volatile(
        "mma.sync.aligned.m16n8k16.row.col.f32.f16.f16.f32 "
        "{%0,%1,%2,%3}, {%4,%5,%6,%7}, {%8,%9}, {%0,%1,%2,%3};"
        : "+f"(c[0]), "+f"(c[1]), "+f"(c[2]), "+f"(c[3])
        : "r"(a[0]), "r"(a[1]), "r"(a[2]), "r"(a[3]), "r"(b0), "r"(b1));
}

// ---------------- fused prep: A blocks (0..511) + B blocks (512..1023) -------
__global__ void k_prep_ab(const float* __restrict__ seq_a,
                          const float* __restrict__ seq_b,
                          const void* __restrict__ mask_a,
                          const void* __restrict__ mask_b,
                          const float* __restrict__ w_word,
                          const float* __restrict__ b_word) {
    __shared__ float s[8][H];
    int bx = blockIdx.x;
    int wid = threadIdx.x >> 5, lane = threadIdx.x & 31;

    if (bx < 512) {  // ---- A: fp16 convert + word + inva ----
        bool mbyte = probe_byte_mask(mask_a);
        int tok0 = bx * 64;
        const float4* pw = (const float4*)w_word;
        float4 w0 = pw[lane], w1v = pw[lane + 32];
        float bw = b_word[0];
#pragma unroll
        for (int i = 0; i < 8; i++) {
            int tok = tok0 + wid * 8 + i;
            const float4* pa = (const float4*)(seq_a + (size_t)tok * H);
            float4 v0 = pa[lane], v1 = pa[lane + 32];
            float ss = dot4(v0, v0) + dot4(v1, v1);
            float dw = dot4(v0, w0) + dot4(v1, w1v);
#pragma unroll
            for (int off = 16; off > 0; off >>= 1) {
                ss += __shfl_xor_sync(0xffffffffu, ss, off);
                dw += __shfl_xor_sync(0xffffffffu, dw, off);
            }
            if (lane == 0) {
                float ma = mask_at(mask_a, tok, mbyte) ? 1.0f : 0.0f;
                g_word[tok] = (dw + bw) * ma;
                g_inva[tok] = 1.0f / (sqrtf(ss) + EPSF);
            }
            size_t base = (size_t)tok * H;
            cvt4h(v0, 1.0f, g_af + base + lane * 4);
            cvt4h(v1, 1.0f, g_af + base + 128 + lane * 4);
        }
    } else {  // ---- B: normalize to fp16, masked partial sums ----
        bool mbyte = probe_byte_mask(mask_b);
        int bi = bx - 512;
        int tok0 = bi * 64;
        int b = tok0 >> 10;
        int chunk = bi & 15;
        float4 acc0 = {0.f, 0.f, 0.f, 0.f}, acc1 = {0.f, 0.f, 0.f, 0.f};
#pragma unroll
        for (int i = 0; i < 8; i++) {
            int tok = tok0 + wid * 8 + i;
            const float4* p = (const float4*)(seq_b + (size_t)tok * H);
            float4 v0 = p[lane], v1 = p[lane + 32];
            float ss = dot4(v0, v0) + dot4(v1, v1);
#pragma unroll
            for (int off = 16; off > 0; off >>= 1)
                ss += __shfl_xor_sync(0xffffffffu, ss, off);
            float ib = 1.0f / (sqrtf(ss) + EPSF);
            size_t base = (size_t)tok * H;
            cvt4h(v0, ib, g_bh + base + lane * 4);
            cvt4h(v1, ib, g_bh + base + 128 + lane * 4);
            if (mask_at(mask_b, tok, mbyte)) {
                acc0.x += v0.x * ib; acc0.y += v0.y * ib;
                acc0.z += v0.z * ib; acc0.w += v0.w * ib;
                acc1.x += v1.x * ib; acc1.y += v1.y * ib;
                acc1.z += v1.z * ib; acc1.w += v1.w * ib;
            }
        }
        *(float4*)&s[wid][lane * 4] = acc0;
        *(float4*)&s[wid][128 + lane * 4] = acc1;
        __syncthreads();
        int t = threadIdx.x;
        float sum = 0.f;
#pragma unroll
        for (int w = 0; w < 8; w++) sum += s[w][t];
        g_sb_part[chunk][b][t] = sum;
    }
}

// ---------------- HMMA GEMM (fp16 single-pass), 2 CTAs/SM, single wave -------
// Block = 256 threads (8 warps, 4wm x 2wn, warp 32x32). BM=128, A full-K in
// smem (64KB). B chunks 64 n-rows x 64 k-cols (8KB), 4-stage pipeline.
// smem/block 96KB -> 2 CTAs/SM.
#define OFF_B0 4096     // uint4 units
#define B_STAGE 512     // uint4 units (8KB)
#define SMEM_BYTES ((4096 + 4 * B_STAGE) * 16)   // 98304 = 96KB

__global__ __launch_bounds__(256, 2) void k_gemm_max() {
    extern __shared__ __align__(128) unsigned char smraw[];
    const uint32_t smb = smem_u32(smraw);

    const int b   = blockIdx.y;
    const int m0  = blockIdx.x * 128;
    const int tid = threadIdx.x, wid = tid >> 5, lane = tid & 31;
    const int wm = wid & 3, wn = wid >> 2;
    const int g = lane >> 3, ril = lane & 7;

    const uint4* gaf = (const uint4*)g_af + (size_t)(b * NTOK + m0) * 32;
    const uint4* gbh = (const uint4*)g_bh + (size_t)b * NTOK * 32;

    // A: 128 rows x 32 uint4, swizzled; one cp.async group
#pragma unroll
    for (int i = 0; i < 16; i++) {
        int idx = tid + i * 256;
        int r = idx >> 5, c = idx & 31, cs = c ^ (r & 7);
        cpa16(smb + (uint32_t)(r * 32 + cs) * 16, gaf + r * 32 + c);
    }
    asm volatile("cp.async.commit_group;" ::: "memory");

    // B chunk loader: ii -> n-chunk ii>>2 (64 rows), k-chunk ii&3 (64 cols)
    auto loadB = [&](int ii) {
        int nt = ii >> 2, kc = ii & 3, buf = ii & 3;
        uint32_t base = smb + (uint32_t)(OFF_B0 + buf * B_STAGE) * 16;
#pragma unroll
        for (int i = 0; i < 2; i++) {
            int idx = tid + i * 256;
            int n = idx >> 3, c = idx & 7, cs = c ^ (n & 7);
            size_t gi = (size_t)(nt * 64 + n) * 32 + kc * 8 + c;
            cpa16(base + (uint32_t)(n * 8 + cs) * 16, gbh + gi);
        }
        asm volatile("cp.async.commit_group;" ::: "memory");
    };
    loadB(0);
    loadB(1);
    loadB(2);

    float pm[2][2];
    pm[0][0] = pm[0][1] = pm[1][0] = pm[1][1] = -CUDART_INF_F;
    float acc[2][4][4];

    uint32_t fa[2][2][4], fb[2][2][4];

    auto ldfrags = [&](int kc, int ks, int pp, int buf) {
#pragma unroll
        for (int mt = 0; mt < 2; mt++) {
            int r = wm * 32 + mt * 16 + ((g & 1) << 3) + ril;
            int c = kc * 8 + ks * 2 + (g >> 1);
            int cs = c ^ (r & 7);
            ldsm4(smb + (uint32_t)(r * 32 + cs) * 16, fa[pp][mt]);
        }
#pragma unroll
        for (int np = 0; np < 2; np++) {
            int r = wn * 32 + np * 16 + ((g & 1) << 3) + ril;
            int c = ks * 2 + (g >> 1);
            int cs = c ^ (r & 7);
            ldsm4(smb + (uint32_t)(OFF_B0 + buf * B_STAGE + r * 8 + cs) * 16,
                  fb[pp][np]);
        }
    };

    for (int ii = 0; ii < 64; ii++) {
        int kc = ii & 3, buf = ii & 3;
        if (ii <= 61) {
            asm volatile("cp.async.wait_group 2;" ::: "memory");
        } else if (ii == 62) {
            asm volatile("cp.async.wait_group 1;" ::: "memory");
        } else {
            asm volatile("cp.async.wait_group 0;" ::: "memory");
        }
        __syncthreads();
        if (ii <= 60) loadB(ii + 3);

        if (kc == 0) {
#pragma unroll
            for (int mt = 0; mt < 2; mt++)
#pragma unroll
                for (int n = 0; n < 4; n++)
#pragma unroll
                    for (int q = 0; q < 4; q++) acc[mt][n][q] = 0.f;
        }

        ldfrags(kc, 0, 0, buf);
#pragma unroll
        for (int ks = 0; ks < 4; ks++) {
            int cur = ks & 1;
            if (ks < 3) ldfrags(kc, ks + 1, cur ^ 1, buf);
            // B x4 frags: [0]={n0-7,kLo} [1]={n8-15,kLo} [2]={n0-7,kHi} [3]={n8-15,kHi}
#pragma unroll
            for (int mt = 0; mt < 2; mt++)
#pragma unroll
                for (int np = 0; np < 2; np++)
#pragma unroll
                    for (int sub = 0; sub < 2; sub++)
                        mma16816h(acc[mt][np * 2 + sub], fa[cur][mt],
                                  fb[cur][np][sub], fb[cur][np][sub + 2]);
        }

        if (kc == 3) {
#pragma unroll
            for (int mt = 0; mt < 2; mt++)
#pragma unroll
                for (int n = 0; n < 4; n++) {
                    pm[mt][0] = fmaxf(pm[mt][0], fmaxf(acc[mt][n][0], acc[mt][n][1]));
                    pm[mt][1] = fmaxf(pm[mt][1], fmaxf(acc[mt][n][2], acc[mt][n][3]));
                }
        }
    }

    __syncthreads();
    float* mred = (float*)smraw;
#pragma unroll
    for (int mt = 0; mt < 2; mt++)
#pragma unroll
        for (int hf = 0; hf < 2; hf++) {
            float v = pm[mt][hf];
            v = fmaxf(v, __shfl_xor_sync(0xffffffffu, v, 1));
            v = fmaxf(v, __shfl_xor_sync(0xffffffffu, v, 2));
            if ((lane & 3) == 0)
                mred[(wm * 32 + mt * 16 + hf * 8 + (lane >> 2)) * 2 + wn] = v;
        }
    __syncthreads();
    if (tid < 128) {
        float v = fmaxf(mred[tid * 2], mred[tid * 2 + 1]);
        int row = b * NTOK + m0 + tid;
        g_max[row] = v * g_inva[row];
    }
}

// ---------------- final: in-block denom + parallel softmax + MLP -------------
__global__ __launch_bounds__(256) void k_final(
        const float* __restrict__ seq_a,
        const void* __restrict__ mask_a,
        const void* __restrict__ mask_b,
        const float* __restrict__ w1, const float* __restrict__ b1,
        const float* __restrict__ w2, const float* __restrict__ b2,
        float* __restrict__ out) {
    __shared__ float wrd[64], mn[64], mx[64], feat[128], attn[64], sbs[H];
    __shared__ float rr[8], sm4v[4], dnm_part[8];

    int br = blockIdx.x;
    int t  = threadIdx.x;
    int b  = br >> 4;
    int wid = t >> 5, lane = t & 31;

    bool mab = probe_byte_mask(mask_a);
    bool mbb = probe_byte_mask(mask_b);

    if (t < 64) {
        int tok = br * RVL + t;
        wrd[t] = g_word[tok];
        mx[t]  = g_max[tok];
    }
    {
        float s = 0.f;
#pragma unroll
        for (int c = 0; c < 16; c++) s += g_sb_part[c][b][t];
        sbs[t] = s;
    }
    // per-block denom: count mask_b over this batch's 1024 tokens
    {
        int c = 0;
#pragma unroll
        for (int k = 0; k < 4; k++)
            c += mask_at(mask_b, b * NTOK + t + k * 256, mbb) ? 1 : 0;
#pragma unroll
        for (int off = 16; off > 0; off >>= 1)
            c += __shfl_xor_sync(0xffffffffu, c, off);
        if (lane == 0) dnm_part[wid] = (float)c;
    }
    __syncthreads();

    // ---- parallel masked softmax over 64 tokens (threads 0..63) ----
    float sft = NEGV, ev = 0.f;
    if (t < 64)
        sft = mask_at(mask_a, br * RVL + t, mab) ? wrd[t] : NEGV;
    if (t < 64) {
        float m = sft;
#pragma unroll
        for (int off = 16; off > 0; off >>= 1)
            m = fmaxf(m, __shfl_xor_sync(0xffffffffu, m, off));
        if (lane == 0) sm4v[wid] = m;
    }
    __syncthreads();
    if (t < 64) {
        float M = fmaxf(sm4v[0], sm4v[1]);
        ev = expf(sft - M);
        float s = ev;
#pragma unroll
        for (int off = 16; off > 0; off >>= 1)
            s += __shfl_xor_sync(0xffffffffu, s, off);
        if (lane == 0) sm4v[2 + wid] = s;
    }
    __syncthreads();
    if (t < 64) attn[t] = ev / (sm4v[2] + sm4v[3]);

    // ---- masked mean: thread = (row t>>2, quarter t&3); 16 independent LDG.128
    {
        float dnm = 0.f;
#pragma unroll
        for (int w = 0; w < 8; w++) dnm += dnm_part[w];
        dnm = fmaxf(dnm, 1.0f);
        int row = t >> 2, q = t & 3;
        const float4* pa = (const float4*)(seq_a + ((size_t)(br * RVL + row)) * H) + q * 16;
        const float4* sq = (const float4*)(sbs + q * 64);
        float ds = 0.f;
#pragma unroll
        for (int j = 0; j < 16; j++) ds += dot4(pa[j], sq[j]);
        ds += __shfl_xor_sync(0xffffffffu, ds, 1);
        ds += __shfl_xor_sync(0xffffffffu, ds, 2);
        if (q == 0) mn[row] = g_inva[br * RVL + row] * ds / dnm;
    }
    __syncthreads();

    if (t < 128) {
        int l = t >> 1;
        feat[t] = ((t & 1) ? mx[l] : mn[l]) * wrd[l];
    }
    __syncthreads();

    // ---- MLP: hid = tanh(feat @ w1 + b1); logit = hid @ w2 + b2 ----
    {
        float acc = b1[t];
#pragma unroll 4
        for (int f = 0; f < 128; f++) acc += feat[f] * w1[f * HID + t];
        float v = tanhf(acc) * w2[t];
#pragma unroll
        for (int off = 16; off > 0; off >>= 1)
            v += __shfl_xor_sync(0xffffffffu, v, off);
        if (lane == 0) rr[wid] = v;
    }
    __syncthreads();
    if (t == 0) {
        float s = 0.f;
#pragma unroll
        for (int w = 0; w < 8; w++) s += rr[w];
        out[br] = s + b2[0];
    }

    // ---- aggregation: column t over 64 rows, 8-load batches ----
    {
        const float* A = seq_a + (size_t)br * RVL * H + t;
        float agg = 0.f;
#pragma unroll
        for (int gq = 0; gq < 8; gq++) {
            float v0 = A[(gq * 8 + 0) * H], v1 = A[(gq * 8 + 1) * H];
            float v2 = A[(gq * 8 + 2) * H], v3 = A[(gq * 8 + 3) * H];
            float v4 = A[(gq * 8 + 4) * H], v5 = A[(gq * 8 + 5) * H];
            float v6 = A[(gq * 8 + 6) * H], v7 = A[(gq * 8 + 7) * H];
            agg += attn[gq * 8 + 0] * v0 + attn[gq * 8 + 1] * v1 +
                   attn[gq * 8 + 2] * v2 + attn[gq * 8 + 3] * v3 +
                   attn[gq * 8 + 4] * v4 + attn[gq * 8 + 5] * v5 +
                   attn[gq * 8 + 6] * v6 + attn[gq * 8 + 7] * v7;
        }
        out[BZ * RVN + br * H + t] = agg;
    }
}

// ---------------- launch ------------------------------------------------------
extern "C" void kernel_launch(void* const* d_in, const int* in_sizes, int n_in,
                              void* d_out, int out_size) {
    const float* seq_a = (const float*)d_in[0];
    const float* seq_b = (const float*)d_in[1];
    const void*  mask_a = d_in[2];
    const void*  mask_b = d_in[3];
    const float* w_word = (const float*)d_in[4];
    const float* b_word = (const float*)d_in[5];
    const float* w1 = (const float*)d_in[6];
    const float* b1 = (const float*)d_in[7];
    const float* w2 = (const float*)d_in[8];
    const float* b2 = (const float*)d_in[9];
    float* out = (float*)d_out;

    cudaFuncSetAttribute(k_gemm_max, cudaFuncAttributeMaxDynamicSharedMemorySize,
                         SMEM_BYTES);

    k_prep_ab<<<1024, 256>>>(seq_a, seq_b, mask_a, mask_b, w_word, b_word);
    k_gemm_max<<<dim3(8, BZ), 256, SMEM_BYTES>>>();
    k_final<<<BZ * RVN, 256>>>(seq_a, mask_a, mask_b, w1, b1, w2, b2, out);
}

// round 17
// speedup vs baseline: 1.6003x; 1.0400x over previous
#include <cuda_runtime.h>
#include <cuda_fp16.h>
#include <math_constants.h>
#include <cstdint>

#define BZ   32
#define RVN  16
#define RVL  64
#define H    256
#define NTOK 1024
#define HID  256
#define EPSF 1e-8f
#define NEGV -100000000.0f

// ---------------- scratch ----------------------------------------------------
__device__ __align__(16) float g_sb_part[16][BZ][H];
__device__ __align__(16) float g_word[BZ * NTOK];
__device__ __align__(16) float g_inva[BZ * NTOK];
__device__ __align__(16) float g_max[BZ * NTOK];
// fp16 operands: A raw fp16; B pre-scaled by 1/||b|| fp16
__device__ __align__(16) __half g_af[BZ * NTOK * H];
__device__ __align__(16) __half g_bh[BZ * NTOK * H];

// Warp-local mask dtype probe (bool-byte vs 4-byte masks)
__device__ __forceinline__ bool probe_byte_mask(const void* m) {
    int lane = threadIdx.x & 31;
    unsigned char v = ((const unsigned char*)m)[lane * 4 + 1];
    return __popc(__ballot_sync(0xffffffffu, v != 0)) >= 4;
}
__device__ __forceinline__ bool mask_at(const void* m, int i, bool isbyte) {
    if (isbyte) return ((const unsigned char*)m)[i] != 0;
    return ((const unsigned int*)m)[i] != 0u;
}
__device__ __forceinline__ float dot4(float4 a, float4 b) {
    return a.x * b.x + a.y * b.y + a.z * b.z + a.w * b.w;
}
__device__ __forceinline__ void cvt4h(float4 v, float s, __half* p) {
    __half2* d = (__half2*)p;
    d[0] = __floats2half2_rn(v.x * s, v.y * s);
    d[1] = __floats2half2_rn(v.z * s, v.w * s);
}

__device__ __forceinline__ uint32_t smem_u32(const void* p) {
    uint32_t a;
    asm("{ .reg .u64 t; cvta.to.shared.u64 t, %1; cvt.u32.u64 %0, t; }"
        : "=r"(a) : "l"(p));
    return a;
}
__device__ __forceinline__ void cpa16(uint32_t dst, const void* src) {
    asm volatile("cp.async.cg.shared.global [%0], [%1], 16;" :: "r"(dst), "l"(src));
}
__device__ __forceinline__ void ldsm4(uint32_t addr, uint32_t* r) {
    asm volatile("ldmatrix.sync.aligned.m8n8.x4.shared.b16 {%0,%1,%2,%3}, [%4];"
                 : "=r"(r[0]), "=r"(r[1]), "=r"(r[2]), "=r"(r[3]) : "r"(addr));
}
__device__ __forceinline__ void mma16816h(float* c, const uint32_t* a,
                                          uint32_t b0, uint32_t b1) {
    asm volatile(
        "mma.sync.aligned.m16n8k16.row.col.f32.f16.f16.f32 "
        "{%0,%1,%2,%3}, {%4,%5,%6,%7}, {%8,%9}, {%0,%1,%2,%3};"
        : "+f"(c[0]), "+f"(c[1]), "+f"(c[2]), "+f"(c[3])
        : "r"(a[0]), "r"(a[1]), "r"(a[2]), "r"(a[3]), "r"(b0), "r"(b1));
}

// ---------------- fused prep: A blocks (0..511) + B blocks (512..1023) -------
__global__ void k_prep_ab(const float* __restrict__ seq_a,
                          const float* __restrict__ seq_b,
                          const void* __restrict__ mask_a,
                          const void* __restrict__ mask_b,
                          const float* __restrict__ w_word,
                          const float* __restrict__ b_word) {
    __shared__ float s[8][H];
    int bx = blockIdx.x;
    int wid = threadIdx.x >> 5, lane = threadIdx.x & 31;

    if (bx < 512) {  // ---- A: fp16 convert + word + inva ----
        bool mbyte = probe_byte_mask(mask_a);
        int tok0 = bx * 64;
        const float4* pw = (const float4*)w_word;
        float4 w0 = pw[lane], w1v = pw[lane + 32];
        float bw = b_word[0];
#pragma unroll
        for (int i = 0; i < 8; i++) {
            int tok = tok0 + wid * 8 + i;
            const float4* pa = (const float4*)(seq_a + (size_t)tok * H);
            float4 v0 = pa[lane], v1 = pa[lane + 32];
            float ss = dot4(v0, v0) + dot4(v1, v1);
            float dw = dot4(v0, w0) + dot4(v1, w1v);
#pragma unroll
            for (int off = 16; off > 0; off >>= 1) {
                ss += __shfl_xor_sync(0xffffffffu, ss, off);
                dw += __shfl_xor_sync(0xffffffffu, dw, off);
            }
            if (lane == 0) {
                float ma = mask_at(mask_a, tok, mbyte) ? 1.0f : 0.0f;
                g_word[tok] = (dw + bw) * ma;
                g_inva[tok] = 1.0f / (sqrtf(ss) + EPSF);
            }
            size_t base = (size_t)tok * H;
            cvt4h(v0, 1.0f, g_af + base + lane * 4);
            cvt4h(v1, 1.0f, g_af + base + 128 + lane * 4);
        }
    } else {  // ---- B: normalize to fp16, masked partial sums ----
        bool mbyte = probe_byte_mask(mask_b);
        int bi = bx - 512;
        int tok0 = bi * 64;
        int b = tok0 >> 10;
        int chunk = bi & 15;
        float4 acc0 = {0.f, 0.f, 0.f, 0.f}, acc1 = {0.f, 0.f, 0.f, 0.f};
#pragma unroll
        for (int i = 0; i < 8; i++) {
            int tok = tok0 + wid * 8 + i;
            const float4* p = (const float4*)(seq_b + (size_t)tok * H);
            float4 v0 = p[lane], v1 = p[lane + 32];
            float ss = dot4(v0, v0) + dot4(v1, v1);
#pragma unroll
            for (int off = 16; off > 0; off >>= 1)
                ss += __shfl_xor_sync(0xffffffffu, ss, off);
            float ib = 1.0f / (sqrtf(ss) + EPSF);
            size_t base = (size_t)tok * H;
            cvt4h(v0, ib, g_bh + base + lane * 4);
            cvt4h(v1, ib, g_bh + base + 128 + lane * 4);
            if (mask_at(mask_b, tok, mbyte)) {
                acc0.x += v0.x * ib; acc0.y += v0.y * ib;
                acc0.z += v0.z * ib; acc0.w += v0.w * ib;
                acc1.x += v1.x * ib; acc1.y += v1.y * ib;
                acc1.z += v1.z * ib; acc1.w += v1.w * ib;
            }
        }
        *(float4*)&s[wid][lane * 4] = acc0;
        *(float4*)&s[wid][128 + lane * 4] = acc1;
        __syncthreads();
        int t = threadIdx.x;
        float sum = 0.f;
#pragma unroll
        for (int w = 0; w < 8; w++) sum += s[w][t];
        g_sb_part[chunk][b][t] = sum;
    }
}

// ---------------- HMMA GEMM (fp16 single-pass), 2 CTAs/SM, single wave -------
// Block = 256 threads (8 warps, 4wm x 2wn, warp 32x32). BM=128, A full-K in
// smem (64KB). B stages: 64 n-rows x 128 k-cols (16KB), 3-stage pipeline ->
// 32 iterations (16 n-chunks x 2 k-halves). smem 112KB -> 2 CTAs/SM.
#define OFF_B0 4096     // uint4 units
#define B_STAGE 1024    // uint4 units (16KB)
#define SMEM_BYTES ((4096 + 3 * B_STAGE) * 16)   // 114688 = 112KB

__global__ __launch_bounds__(256, 2) void k_gemm_max() {
    extern __shared__ __align__(128) unsigned char smraw[];
    const uint32_t smb = smem_u32(smraw);

    const int b   = blockIdx.y;
    const int m0  = blockIdx.x * 128;
    const int tid = threadIdx.x, wid = tid >> 5, lane = tid & 31;
    const int wm = wid & 3, wn = wid >> 2;
    const int g = lane >> 3, ril = lane & 7;

    const uint4* gaf = (const uint4*)g_af + (size_t)(b * NTOK + m0) * 32;
    const uint4* gbh = (const uint4*)g_bh + (size_t)b * NTOK * 32;

    // A: 128 rows x 32 uint4, swizzled; one cp.async group
#pragma unroll
    for (int i = 0; i < 16; i++) {
        int idx = tid + i * 256;
        int r = idx >> 5, c = idx & 31, cs = c ^ (r & 7);
        cpa16(smb + (uint32_t)(r * 32 + cs) * 16, gaf + r * 32 + c);
    }
    asm volatile("cp.async.commit_group;" ::: "memory");

    // B stage loader: ii -> n-chunk ii>>1 (64 rows), k-half ii&1 (128 cols)
    // Stage layout: 64 rows x 16 uint4/row, swizzled.
    auto loadB = [&](int ii) {
        int nt = ii >> 1, kh = ii & 1, buf = ii % 3;
        uint32_t base = smb + (uint32_t)(OFF_B0 + buf * B_STAGE) * 16;
#pragma unroll
        for (int i = 0; i < 4; i++) {
            int idx = tid + i * 256;
            int n = idx >> 4, c = idx & 15, cs = c ^ (n & 7);
            size_t gi = (size_t)(nt * 64 + n) * 32 + kh * 16 + c;
            cpa16(base + (uint32_t)(n * 16 + cs) * 16, gbh + gi);
        }
        asm volatile("cp.async.commit_group;" ::: "memory");
    };
    loadB(0);
    loadB(1);

    float pm[2][2];
    pm[0][0] = pm[0][1] = pm[1][0] = pm[1][1] = -CUDART_INF_F;
    float acc[2][4][4];

    uint32_t fa[2][2][4], fb[2][2][4];

    auto ldfrags = [&](int kh, int ks, int pp, int buf) {
#pragma unroll
        for (int mt = 0; mt < 2; mt++) {
            int r = wm * 32 + mt * 16 + ((g & 1) << 3) + ril;
            int c = kh * 16 + ks * 2 + (g >> 1);
            int cs = c ^ (r & 7);
            ldsm4(smb + (uint32_t)(r * 32 + cs) * 16, fa[pp][mt]);
        }
#pragma unroll
        for (int np = 0; np < 2; np++) {
            int r = wn * 32 + np * 16 + ((g & 1) << 3) + ril;
            int c = ks * 2 + (g >> 1);
            int cs = c ^ (r & 7);
            ldsm4(smb + (uint32_t)(OFF_B0 + buf * B_STAGE + r * 16 + cs) * 16,
                  fb[pp][np]);
        }
    };

    for (int ii = 0; ii < 32; ii++) {
        int kh = ii & 1, buf = ii % 3;
        if (ii < 31) {
            asm volatile("cp.async.wait_group 1;" ::: "memory");
        } else {
            asm volatile("cp.async.wait_group 0;" ::: "memory");
        }
        __syncthreads();
        if (ii <= 29) loadB(ii + 2);

        if (kh == 0) {
#pragma unroll
            for (int mt = 0; mt < 2; mt++)
#pragma unroll
                for (int n = 0; n < 4; n++)
#pragma unroll
                    for (int q = 0; q < 4; q++) acc[mt][n][q] = 0.f;
        }

        ldfrags(kh, 0, 0, buf);
#pragma unroll
        for (int ks = 0; ks < 8; ks++) {
            int cur = ks & 1;
            if (ks < 7) ldfrags(kh, ks + 1, cur ^ 1, buf);
            // B x4 frags: [0]={n0-7,kLo} [1]={n8-15,kLo} [2]={n0-7,kHi} [3]={n8-15,kHi}
#pragma unroll
            for (int mt = 0; mt < 2; mt++)
#pragma unroll
                for (int np = 0; np < 2; np++)
#pragma unroll
                    for (int sub = 0; sub < 2; sub++)
                        mma16816h(acc[mt][np * 2 + sub], fa[cur][mt],
                                  fb[cur][np][sub], fb[cur][np][sub + 2]);
        }

        if (kh == 1) {
#pragma unroll
            for (int mt = 0; mt < 2; mt++)
#pragma unroll
                for (int n = 0; n < 4; n++) {
                    pm[mt][0] = fmaxf(pm[mt][0], fmaxf(acc[mt][n][0], acc[mt][n][1]));
                    pm[mt][1] = fmaxf(pm[mt][1], fmaxf(acc[mt][n][2], acc[mt][n][3]));
                }
        }
    }

    __syncthreads();
    float* mred = (float*)smraw;
#pragma unroll
    for (int mt = 0; mt < 2; mt++)
#pragma unroll
        for (int hf = 0; hf < 2; hf++) {
            float v = pm[mt][hf];
            v = fmaxf(v, __shfl_xor_sync(0xffffffffu, v, 1));
            v = fmaxf(v, __shfl_xor_sync(0xffffffffu, v, 2));
            if ((lane & 3) == 0)
                mred[(wm * 32 + mt * 16 + hf * 8 + (lane >> 2)) * 2 + wn] = v;
        }
    __syncthreads();
    if (tid < 128) {
        float v = fmaxf(mred[tid * 2], mred[tid * 2 + 1]);
        int row = b * NTOK + m0 + tid;
        g_max[row] = v * g_inva[row];
    }
}

// ---------------- final: in-block denom + parallel softmax + MLP -------------
__global__ __launch_bounds__(256) void k_final(
        const float* __restrict__ seq_a,
        const void* __restrict__ mask_a,
        const void* __restrict__ mask_b,
        const float* __restrict__ w1, const float* __restrict__ b1,
        const float* __restrict__ w2, const float* __restrict__ b2,
        float* __restrict__ out) {
    __shared__ float wrd[64], mn[64], mx[64], feat[128], attn[64], sbs[H];
    __shared__ float rr[8], sm4v[4], dnm_part[8];

    int br = blockIdx.x;
    int t  = threadIdx.x;
    int b  = br >> 4;
    int wid = t >> 5, lane = t & 31;

    bool mab = probe_byte_mask(mask_a);
    bool mbb = probe_byte_mask(mask_b);

    if (t < 64) {
        int tok = br * RVL + t;
        wrd[t] = g_word[tok];
        mx[t]  = g_max[tok];
    }
    {
        float s = 0.f;
#pragma unroll
        for (int c = 0; c < 16; c++) s += g_sb_part[c][b][t];
        sbs[t] = s;
    }
    // per-block denom: count mask_b over this batch's 1024 tokens
    {
        int c = 0;
#pragma unroll
        for (int k = 0; k < 4; k++)
            c += mask_at(mask_b, b * NTOK + t + k * 256, mbb) ? 1 : 0;
#pragma unroll
        for (int off = 16; off > 0; off >>= 1)
            c += __shfl_xor_sync(0xffffffffu, c, off);
        if (lane == 0) dnm_part[wid] = (float)c;
    }
    __syncthreads();

    // ---- parallel masked softmax over 64 tokens (threads 0..63) ----
    float sft = NEGV, ev = 0.f;
    if (t < 64)
        sft = mask_at(mask_a, br * RVL + t, mab) ? wrd[t] : NEGV;
    if (t < 64) {
        float m = sft;
#pragma unroll
        for (int off = 16; off > 0; off >>= 1)
            m = fmaxf(m, __shfl_xor_sync(0xffffffffu, m, off));
        if (lane == 0) sm4v[wid] = m;
    }
    __syncthreads();
    if (t < 64) {
        float M = fmaxf(sm4v[0], sm4v[1]);
        ev = expf(sft - M);
        float s = ev;
#pragma unroll
        for (int off = 16; off > 0; off >>= 1)
            s += __shfl_xor_sync(0xffffffffu, s, off);
        if (lane == 0) sm4v[2 + wid] = s;
    }
    __syncthreads();
    if (t < 64) attn[t] = ev / (sm4v[2] + sm4v[3]);

    // ---- masked mean from fp16 A: thread = (row t>>2, quarter t&3) ----
    // quarter = 64 halves = 8 uint4 independent loads
    {
        float dnm = 0.f;
#pragma unroll
        for (int w = 0; w < 8; w++) dnm += dnm_part[w];
        dnm = fmaxf(dnm, 1.0f);
        int row = t >> 2, q = t & 3;
        const uint4* pa = (const uint4*)(g_af + ((size_t)(br * RVL + row)) * H) + q * 8;
        const float* sq = sbs + q * 64;
        float ds = 0.f;
#pragma unroll
        for (int j = 0; j < 8; j++) {
            uint4 u = pa[j];
            const __half2* h2 = (const __half2*)&u;
#pragma unroll
            for (int e = 0; e < 4; e++) {
                float2 f = __half22float2(h2[e]);
                ds += f.x * sq[j * 8 + e * 2] + f.y * sq[j * 8 + e * 2 + 1];
            }
        }
        ds += __shfl_xor_sync(0xffffffffu, ds, 1);
        ds += __shfl_xor_sync(0xffffffffu, ds, 2);
        if (q == 0) mn[row] = g_inva[br * RVL + row] * ds / dnm;
    }
    __syncthreads();

    if (t < 128) {
        int l = t >> 1;
        feat[t] = ((t & 1) ? mx[l] : mn[l]) * wrd[l];
    }
    __syncthreads();

    // ---- MLP: hid = tanh(feat @ w1 + b1); logit = hid @ w2 + b2 ----
    {
        float acc = b1[t];
#pragma unroll 4
        for (int f = 0; f < 128; f++) acc += feat[f] * w1[f * HID + t];
        float v = tanhf(acc) * w2[t];
#pragma unroll
        for (int off = 16; off > 0; off >>= 1)
            v += __shfl_xor_sync(0xffffffffu, v, off);
        if (lane == 0) rr[wid] = v;
    }
    __syncthreads();
    if (t == 0) {
        float s = 0.f;
#pragma unroll
        for (int w = 0; w < 8; w++) s += rr[w];
        out[br] = s + b2[0];
    }

    // ---- aggregation (fp32 seq_a): column t over 64 rows, 8-load batches ----
    {
        const float* A = seq_a + (size_t)br * RVL * H + t;
        float agg = 0.f;
#pragma unroll
        for (int gq = 0; gq < 8; gq++) {
            float v0 = A[(gq * 8 + 0) * H], v1 = A[(gq * 8 + 1) * H];
            float v2 = A[(gq * 8 + 2) * H], v3 = A[(gq * 8 + 3) * H];
            float v4 = A[(gq * 8 + 4) * H], v5 = A[(gq * 8 + 5) * H];
            float v6 = A[(gq * 8 + 6) * H], v7 = A[(gq * 8 + 7) * H];
            agg += attn[gq * 8 + 0] * v0 + attn[gq * 8 + 1] * v1 +
                   attn[gq * 8 + 2] * v2 + attn[gq * 8 + 3] * v3 +
                   attn[gq * 8 + 4] * v4 + attn[gq * 8 + 5] * v5 +
                   attn[gq * 8 + 6] * v6 + attn[gq * 8 + 7] * v7;
        }
        out[BZ * RVN + br * H + t] = agg;
    }
}

// ---------------- launch ------------------------------------------------------
extern "C" void kernel_launch(void* const* d_in, const int* in_sizes, int n_in,
                              void* d_out, int out_size) {
    const float* seq_a = (const float*)d_in[0];
    const float* seq_b = (const float*)d_in[1];
    const void*  mask_a = d_in[2];
    const void*  mask_b = d_in[3];
    const float* w_word = (const float*)d_in[4];
    const float* b_word = (const float*)d_in[5];
    const float* w1 = (const float*)d_in[6];
    const float* b1 = (const float*)d_in[7];
    const float* w2 = (const float*)d_in[8];
    const float* b2 = (const float*)d_in[9];
    float* out = (float*)d_out;

    cudaFuncSetAttribute(k_gemm_max, cudaFuncAttributeMaxDynamicSharedMemorySize,
                         SMEM_BYTES);

    k_prep_ab<<<1024, 256>>>(seq_a, seq_b, mask_a, mask_b, w_word, b_word);
    k_gemm_max<<<dim3(8, BZ), 256, SMEM_BYTES>>>();
    k_final<<<BZ * RVN, 256>>>(seq_a, mask_a, mask_b, w1, b1, w2, b2, out);
}